// round 6
// baseline (speedup 1.0000x reference)
#include <cuda_runtime.h>
#include <cstdint>

#define BZ 8
#define NF 10000
#define DD 16
#define HH 512
#define WW 512
#define NPIX (BZ * HH * WW)
#define HWPIX (HH * WW)
#define NREC (BZ * NF)
#define RECQ 12      // float4 per source record (192 B)
#define RECQP 16     // float4 per padded record (256 B, line-aligned)

// 20.48 MB padded attribute table (line-aligned records)
__device__ __align__(256) float4 g_pad[(size_t)NREC * RECQP];

__global__ __launch_bounds__(256) void prep_kernel(const float4* __restrict__ attrs) {
    int i = blockIdx.x * blockDim.x + threadIdx.x;   // over NREC*RECQ float4s
    if (i >= NREC * RECQ) return;
    int r = i / RECQ;
    int q = i - r * RECQ;
    g_pad[(size_t)r * RECQP + q] = attrs[i];
}

#define TPB 512
#define PPB (TPB / 8)    // 64 pixels per block, 8 lanes per pixel

__global__ __launch_bounds__(TPB) void renderer_kernel(
    const float* __restrict__ baryw,     // [BZ,H,W,3]
    const int*   __restrict__ tri,       // [BZ,H,W]
    float*       __restrict__ out)       // [BZ, D+1, H, W]
{
    __shared__ float stage[PPB * 20];    // stride 20: conflict-free + 16B aligned

    const int tid = threadIdx.x;
    const int pl  = tid >> 3;            // pixel slot 0..63
    const int j   = tid & 7;             // lane within pixel
    const int p   = blockIdx.x * PPB + pl;

    int t = tri[p];
    bool fg = (t >= 0);
    int ti = fg ? t : 0;
    float m  = fg ? 1.0f : 0.0f;
    float w0 = baryw[p * 3 + 0] * m;
    float w1 = baryw[p * 3 + 1] * m;
    float w2 = baryw[p * 3 + 2] * m;

    // Gather from padded record: lanes 0..7 cover bytes [0,128) = ONE line
    // (v0 quads 0-3 + v1 quads 0-3). Lanes 0..3 additionally pull v2's 64 B.
    const float4* rec = g_pad + (size_t)ti * RECQP;
    float4 A = rec[j];
    float4 P;
    if (j < 4) {
        float4 C = rec[8 + j];           // v2 quad j (line 1, sectors 0-3)
        P.x = fmaf(w0, A.x, w2 * C.x);
        P.y = fmaf(w0, A.y, w2 * C.y);
        P.z = fmaf(w0, A.z, w2 * C.z);
        P.w = fmaf(w0, A.w, w2 * C.w);
    } else {
        P.x = w1 * A.x; P.y = w1 * A.y; P.z = w1 * A.z; P.w = w1 * A.w;
    }
    // combine v1 partial (lanes j+4) into lanes j<4
    P.x += __shfl_xor_sync(0xffffffffu, P.x, 4);
    P.y += __shfl_xor_sync(0xffffffffu, P.y, 4);
    P.z += __shfl_xor_sync(0xffffffffu, P.z, 4);
    P.w += __shfl_xor_sync(0xffffffffu, P.w, 4);

    if (j < 4)
        *(float4*)&stage[pl * 20 + 4 * j] = P;   // ch 4j..4j+3
    if (j == 0)
        stage[pl * 20 + 16] = m;                  // visibility
    __syncthreads();

    // Store phase: one line per STG instruction (32 consecutive pixels, one channel)
    const int n   = (blockIdx.x * PPB) / HWPIX;   // 64 | HWPIX -> whole CTA in one image
    const int hw0 = blockIdx.x * PPB - n * HWPIX;
    float* ob = out + (size_t)n * (DD + 1) * HWPIX + hw0;

    if (tid < 256) {
        int px = tid & 63;
        int q  = tid >> 6;                        // channel quad 0..3
        float4 v = *(const float4*)&stage[px * 20 + 4 * q];
        ob[(size_t)(4 * q + 0) * HWPIX + px] = v.x;
        ob[(size_t)(4 * q + 1) * HWPIX + px] = v.y;
        ob[(size_t)(4 * q + 2) * HWPIX + px] = v.z;
        ob[(size_t)(4 * q + 3) * HWPIX + px] = v.w;
    } else if (tid < 320) {
        int px = tid - 256;
        ob[(size_t)DD * HWPIX + px] = stage[px * 20 + 16];
    }
}

extern "C" void kernel_launch(void* const* d_in, const int* in_sizes, int n_in,
                              void* d_out, int out_size) {
    const float4* attrs = (const float4*)d_in[0];
    const float*  baryw = (const float*)d_in[1];
    const int*    tri   = (const int*)d_in[2];
    float*        out   = (float*)d_out;

    int prep_n = NREC * RECQ;
    prep_kernel<<<(prep_n + 255) / 256, 256>>>(attrs);

    renderer_kernel<<<NPIX / PPB, TPB>>>(baryw, tri, out);
}

// round 8
// speedup vs baseline: 1.3202x; 1.3202x over previous
#include <cuda_runtime.h>
#include <cstdint>

#define BZ 8
#define NF 10000
#define DD 16
#define HH 512
#define WW 512
#define NPIX (BZ * HH * WW)
#define HWPIX (HH * WW)

#define TPB 256
#define SLOTS 32            // TPB/8 pixel-slots, 8 lanes each
#define PPB 64              // 2 pixels per slot

__global__ __launch_bounds__(TPB) void renderer_kernel(
    const float4* __restrict__ attrs,    // records of 12 float4, stride 192 B
    const float*  __restrict__ baryw,    // [BZ,H,W,3]
    const int*    __restrict__ tri,      // [BZ,H,W]
    float*        __restrict__ out)      // [BZ, D+1, H, W]
{
    __shared__ float stage[PPB * 20];    // stride 20: conflict-free, 16B-aligned rows

    const int tid  = threadIdx.x;
    const int slot = tid >> 3;           // 0..31
    const int j    = tid & 7;            // lane within pixel
    const int base = blockIdx.x * PPB;
    const int p0   = base + slot;        // chain 0
    const int p1   = p0 + SLOTS;         // chain 1 (independent)

    // --- two independent dependent-chains, loads batched up front ---
    int t0 = tri[p0];
    int t1 = tri[p1];
    bool fg0 = (t0 >= 0), fg1 = (t1 >= 0);
    int ti0 = fg0 ? t0 : 0, ti1 = fg1 ? t1 : 0;
    float m0 = fg0 ? 1.0f : 0.0f, m1 = fg1 ? 1.0f : 0.0f;

    float w00 = baryw[p0 * 3 + 0] * m0;
    float w01 = baryw[p0 * 3 + 1] * m0;
    float w02 = baryw[p0 * 3 + 2] * m0;
    float w10 = baryw[p1 * 3 + 0] * m1;
    float w11 = baryw[p1 * 3 + 1] * m1;
    float w12 = baryw[p1 * 3 + 2] * m1;

    const float4* rec0 = attrs + (size_t)ti0 * 12;
    const float4* rec1 = attrs + (size_t)ti1 * 12;

    // lanes 0..7 cover v0+v1 (bytes [0,128) of record); lanes 0..3 also pull v2
    float4 A0 = rec0[j];
    float4 A1 = rec1[j];
    float4 P0, P1;
    if (j < 4) {
        float4 C0 = rec0[8 + j];
        float4 C1 = rec1[8 + j];
        P0.x = fmaf(w00, A0.x, w02 * C0.x);
        P0.y = fmaf(w00, A0.y, w02 * C0.y);
        P0.z = fmaf(w00, A0.z, w02 * C0.z);
        P0.w = fmaf(w00, A0.w, w02 * C0.w);
        P1.x = fmaf(w10, A1.x, w12 * C1.x);
        P1.y = fmaf(w10, A1.y, w12 * C1.y);
        P1.z = fmaf(w10, A1.z, w12 * C1.z);
        P1.w = fmaf(w10, A1.w, w12 * C1.w);
    } else {
        P0.x = w01 * A0.x; P0.y = w01 * A0.y; P0.z = w01 * A0.z; P0.w = w01 * A0.w;
        P1.x = w11 * A1.x; P1.y = w11 * A1.y; P1.z = w11 * A1.z; P1.w = w11 * A1.w;
    }
    // fold v1 partials (lanes j+4) into lanes j<4
    P0.x += __shfl_xor_sync(0xffffffffu, P0.x, 4);
    P0.y += __shfl_xor_sync(0xffffffffu, P0.y, 4);
    P0.z += __shfl_xor_sync(0xffffffffu, P0.z, 4);
    P0.w += __shfl_xor_sync(0xffffffffu, P0.w, 4);
    P1.x += __shfl_xor_sync(0xffffffffu, P1.x, 4);
    P1.y += __shfl_xor_sync(0xffffffffu, P1.y, 4);
    P1.z += __shfl_xor_sync(0xffffffffu, P1.z, 4);
    P1.w += __shfl_xor_sync(0xffffffffu, P1.w, 4);

    if (j < 4) {
        *(float4*)&stage[slot * 20 + 4 * j] = P0;
        *(float4*)&stage[(slot + SLOTS) * 20 + 4 * j] = P1;
    }
    if (j == 0) {
        stage[slot * 20 + 16] = m0;
        stage[(slot + SLOTS) * 20 + 16] = m1;
    }
    __syncthreads();

    // --- store phase: each STG warp-instruction = 32 consecutive pixels of one
    // channel = exactly one 128B line ---
    const int n   = base / HWPIX;              // 64 | HWPIX
    const int hw0 = base - n * HWPIX;
    float* ob = out + (size_t)n * (DD + 1) * HWPIX + hw0;

    {
        int px = tid & 63;                     // pixel within block
        int q  = tid >> 6;                     // channel quad 0..3
        float4 v = *(const float4*)&stage[px * 20 + 4 * q];
        ob[(size_t)(4 * q + 0) * HWPIX + px] = v.x;
        ob[(size_t)(4 * q + 1) * HWPIX + px] = v.y;
        ob[(size_t)(4 * q + 2) * HWPIX + px] = v.z;
        ob[(size_t)(4 * q + 3) * HWPIX + px] = v.w;
    }
    if (tid < PPB)
        ob[(size_t)DD * HWPIX + tid] = stage[tid * 20 + 16];
}

extern "C" void kernel_launch(void* const* d_in, const int* in_sizes, int n_in,
                              void* d_out, int out_size) {
    const float4* attrs = (const float4*)d_in[0];
    const float*  baryw = (const float*)d_in[1];
    const int*    tri   = (const int*)d_in[2];
    float*        out   = (float*)d_out;

    renderer_kernel<<<NPIX / PPB, TPB>>>(attrs, baryw, tri, out);
}